// round 16
// baseline (speedup 1.0000x reference)
#include <cuda_runtime.h>
#include <cuda_fp16.h>
#include <stdint.h>
#include <math.h>

// BlockCirculant via FFT:  out = ifft( fft(x*d blocks) * conj(fft(W)) ) + bias
// 4 slots x 128 threads; each slot processes 2 rows per iteration. The einsum
// batches the row PAIR into f32x2 lanes (4 FFMA2 per (i,j) covering both rows),
// halving per-row W traffic and w-prep instructions. fp16 buffers, in-place
// FFT-256 (16x16 Cooley-Tukey), named barriers per slot.

#define K16   16
#define BSZ   256
#define NF    129
#define DIN   4096
#define NB    8192
#define GP    272        // half2 per FFT group scratch (16*17)
#define NSLOT 4
#define TPB   512

// Wf[f*256 + ((ij + 4f) & 255)] = conj(FFT(W[i,j,:]))[f] / 256   (half2)
__device__ __half2 g_Wf[NF * 256];

__device__ __forceinline__ void cmul(float& xr, float& xi, float wr, float wi) {
    float tr = xr * wr - xi * wi;
    xi       = xr * wi + xi * wr;
    xr       = tr;
}

// ---- packed fp32x2 helpers (Blackwell FFMA2) ----
__device__ __forceinline__ unsigned long long pk2(float lo, float hi) {
    unsigned long long r;
    asm("mov.b64 %0, {%1, %2};" : "=l"(r) : "f"(lo), "f"(hi));
    return r;
}
__device__ __forceinline__ float2 upk2(unsigned long long v) {
    float2 r;
    asm("mov.b64 {%0, %1}, %2;" : "=f"(r.x), "=f"(r.y) : "l"(v));
    return r;
}
__device__ __forceinline__ unsigned long long ffma2(unsigned long long a,
                                                    unsigned long long b,
                                                    unsigned long long c) {
    unsigned long long d;
    asm("fma.rn.f32x2 %0, %1, %2, %3;" : "=l"(d) : "l"(a), "l"(b), "l"(c));
    return d;
}
__device__ __forceinline__ void prefetchL2(const void* p) {
    asm volatile("prefetch.global.L2 [%0];" :: "l"(p));
}

template <bool INV>
__device__ __forceinline__ void fft16(float* re, float* im) {
    {
        float tr, ti;
#define SWP(a, b) tr = re[a]; re[a] = re[b]; re[b] = tr; \
                  ti = im[a]; im[a] = im[b]; im[b] = ti;
        SWP(1, 8) SWP(2, 4) SWP(3, 12) SWP(5, 10) SWP(7, 14) SWP(11, 13)
#undef SWP
    }
    constexpr float C1 = 0.923879532511286756f;
    constexpr float S1 = 0.382683432365089772f;
    constexpr float R  = 0.707106781186547524f;
    const float C16[8] = {1.f,  C1,  R,  S1, 0.f, -S1, -R, -C1};
    const float S16[8] = {0.f,  S1,  R,  C1, 1.f,  C1,  R,  S1};
#pragma unroll
    for (int s = 0; s < 4; ++s) {
        const int h = 1 << s;
#pragma unroll
        for (int g = 0; g < 16; g += (h << 1)) {
#pragma unroll
            for (int j = 0; j < h; ++j) {
                const int m = j << (3 - s);
                const float wr = C16[m];
                const float wi = INV ? S16[m] : -S16[m];
                const int a = g + j, b = a + h;
                float tr = re[b] * wr - im[b] * wi;
                float ti = re[b] * wi + im[b] * wr;
                re[b] = re[a] - tr; im[b] = im[a] - ti;
                re[a] += tr;        im[a] += ti;
            }
        }
    }
}

// forward FFT-256 on one group tile (16 threads cooperate), in place
__device__ __forceinline__ void fwd256(__half2* gb, const float2* twf, int t,
                                       float* re, float* im) {
#pragma unroll
    for (int n1 = 0; n1 < 16; ++n1) {
        float2 v = __half22float2(gb[t * 17 + n1]);
        re[n1] = v.x; im[n1] = v.y;
    }
    fft16<false>(re, im);
    __syncwarp();
#pragma unroll
    for (int k1 = 0; k1 < 16; ++k1) {
        if (k1 > 0) {
            float2 w = twf[(t * k1) & 255];
            cmul(re[k1], im[k1], w.x, w.y);
        }
        gb[k1 * 17 + t] = __floats2half2_rn(re[k1], im[k1]);
    }
    __syncwarp();
#pragma unroll
    for (int n2 = 0; n2 < 16; ++n2) {
        float2 v = __half22float2(gb[t * 17 + n2]);
        re[n2] = v.x; im[n2] = v.y;
    }
    fft16<false>(re, im);
    __syncwarp();
#pragma unroll
    for (int k2 = 0; k2 < 16; ++k2)
        gb[(k2 << 4) + t] = __floats2half2_rn(re[k2], im[k2]);
}

// inverse FFT-256 on one group tile; results left in re/im (n = k2*16+t)
__device__ __forceinline__ void inv256(__half2* gb, const float2* twf, int t,
                                       float* re, float* im) {
#pragma unroll
    for (int n1 = 0; n1 < 16; ++n1) {
        float2 v = __half22float2(gb[(n1 << 4) + t]);
        re[n1] = v.x; im[n1] = v.y;
    }
    fft16<true>(re, im);
    __syncwarp();
#pragma unroll
    for (int k1 = 0; k1 < 16; ++k1) {
        if (k1 > 0) {
            float2 w = twf[(t * k1) & 255];
            cmul(re[k1], im[k1], w.x, -w.y);
        }
        gb[k1 * 17 + t] = __floats2half2_rn(re[k1], im[k1]);
    }
    __syncwarp();
#pragma unroll
    for (int n2 = 0; n2 < 16; ++n2) {
        float2 v = __half22float2(gb[t * 17 + n2]);
        re[n2] = v.x; im[n2] = v.y;
    }
    fft16<true>(re, im);
}

// ---------------- W_fft precompute (per launch, cheap) ----------------
__global__ void bc_wfft(const float* __restrict__ W) {
    __shared__ float2 tw[256];
    __shared__ float  wv[256];
    const int ij  = blockIdx.x;      // i*16 + j
    const int tid = threadIdx.x;
    float sv, cv;
    float ang = 6.2831853071795864769f * (float)tid * (1.0f / 256.0f);  // +sign: conj folded
    sincosf(ang, &sv, &cv);
    tw[tid] = make_float2(cv, sv);
    wv[tid] = W[ij * BSZ + tid];
    __syncthreads();
    if (tid < NF) {
        float ar = 0.f, ai = 0.f;
        for (int n = 0; n < 256; ++n) {
            float2 e = tw[(tid * n) & 255];
            ar += wv[n] * e.x;
            ai += wv[n] * e.y;
        }
        g_Wf[tid * 256 + ((ij + 4 * tid) & 255)] =
            __floats2half2_rn(ar * (1.f / 256.f), ai * (1.f / 256.f));
    }
}

// ---------------- main fused kernel ----------------
__global__ void __launch_bounds__(TPB, 1)
bc_main(const float* __restrict__ x, const float* __restrict__ d,
        const float* __restrict__ bias, float* __restrict__ out) {
    extern __shared__ char smem_raw[];
    __half2* Wcs = (__half2*)smem_raw;                          // 132096 B
    float2*  twf = (float2*)(smem_raw + 132096);                //   2048 B
    float*   ds  = (float*) (smem_raw + 132096 + 2048);         //  16384 B
    __half2* bufs = (__half2*)(smem_raw + 150528);              //  69632 B (8 row-buffers)

    const int tid = threadIdx.x;
    {
        const unsigned int* src = (const unsigned int*)g_Wf;
        unsigned int* dst = (unsigned int*)Wcs;
        for (int i2 = tid; i2 < NF * 256; i2 += TPB) dst[i2] = src[i2];
        if (tid < 256) {
            float sv, cv;
            float ang = -6.2831853071795864769f * (float)tid * (1.0f / 256.0f);
            sincosf(ang, &sv, &cv);
            twf[tid] = make_float2(cv, sv);
        }
        for (int i2 = tid; i2 < DIN; i2 += TPB) ds[i2] = d[i2];
    }
    __syncthreads();

    const int slot = tid >> 7;        // 0..3
    const int t128 = tid & 127;
    const int g    = t128 >> 4;       // FFT group 0..7
    const int t    = t128 & 15;       // lane within FFT
    const int barid = slot + 1;
    __half2* ZA = bufs + (2 * slot)     * (8 * GP);
    __half2* ZB = bufs + (2 * slot + 1) * (8 * GP);
    __half2* gA = ZA + g * GP;
    __half2* gB = ZB + g * GP;
    const float4* ds4 = (const float4*)ds;

    float re[16], im[16];

#define BARS() asm volatile("bar.sync %0, 128;" :: "r"(barid) : "memory")

    const int rstride = gridDim.x * (2 * NSLOT);
    const int row0 = blockIdx.x * (2 * NSLOT) + slot * 2;   // always even; rowB=row+1<NB
    if (row0 < NB) {
        prefetchL2((const char*)(x + (size_t)row0 * DIN) + t128 * 128);
        prefetchL2((const char*)(x + (size_t)(row0 + 1) * DIN) + t128 * 128);
    }

    for (int row = row0; row < NB; row += rstride) {
        // ---- P0: load rows A,B (times d), scatter to fp16 FFT tiles ----
#pragma unroll
        for (int r = 0; r < 2; ++r) {
            __half2* Z = r ? ZB : ZA;
            const float4* xr4 = (const float4*)(x + (size_t)(row + r) * DIN);
#pragma unroll
            for (int it = 0; it < 8; ++it) {
                int c4 = t128 + (it << 7);
                float4 xv = xr4[c4];
                float4 dv = ds4[c4];
                float v[4] = {xv.x * dv.x, xv.y * dv.y, xv.z * dv.z, xv.w * dv.w};
#pragma unroll
                for (int e = 0; e < 4; ++e) {
                    int col = (c4 << 2) + e;
                    int p = col >> 9;
                    int n = col & 255;
                    __half* dstp = (__half*)(Z + p * GP + (n & 15) * 17 + (n >> 4));
                    dstp[(col >> 8) & 1] = __float2half(v[e]);
                }
            }
        }
        BARS();

        // prefetch next iteration's rows into L2 (no registers held)
        {
            int nrow = row + rstride;
            if (nrow < NB) {
                prefetchL2((const char*)(x + (size_t)nrow * DIN) + t128 * 128);
                prefetchL2((const char*)(x + (size_t)(nrow + 1) * DIN) + t128 * 128);
            }
        }

        // ---- forward FFT-256 for both rows ----
        fwd256(gA, twf, t, re, im);
        fwd256(gB, twf, t, re, im);
        BARS();

        // ---- einsum: row pair batched into f32x2 lanes ----
        {
            const int f  = t128;            // 0..127
            const int mf = (256 - f) & 255;
            unsigned long long xrr[16], xii[16];
#pragma unroll
            for (int p = 0; p < 8; ++p) {
                float2 aA = __half22float2(ZA[p * GP + f]);
                float2 bA = __half22float2(ZA[p * GP + mf]);
                float2 aB = __half22float2(ZB[p * GP + f]);
                float2 bB = __half22float2(ZB[p * GP + mf]);
                xrr[2 * p]     = pk2(0.5f * (aA.x + bA.x), 0.5f * (aB.x + bB.x));
                xii[2 * p]     = pk2(0.5f * (aA.y - bA.y), 0.5f * (aB.y - bB.y));
                xrr[2 * p + 1] = pk2(0.5f * (aA.y + bA.y), 0.5f * (aB.y + bB.y));
                xii[2 * p + 1] = pk2(0.5f * (bA.x - aA.x), 0.5f * (bB.x - aB.x));
            }
            const uint4* W4 = ((const uint4*)Wcs) + f * 64;   // row f: 256 half2 = 64 uint4
#pragma unroll
            for (int gg = 0; gg < 8; ++gg) {
                unsigned long long P1 = 0ull, Q1 = 0ull, R1 = 0ull, S1 = 0ull;
                unsigned long long P2 = 0ull, Q2 = 0ull, R2 = 0ull, S2 = 0ull;
                const int ia = 2 * gg, ib = 2 * gg + 1;
#pragma unroll
                for (int jc = 0; jc < 4; ++jc) {
                    uint4 wa = W4[(ia * 4 + jc + f) & 63];
                    uint4 wb = W4[(ib * 4 + jc + f) & 63];
                    unsigned int wax[4] = {wa.x, wa.y, wa.z, wa.w};
                    unsigned int wbx[4] = {wb.x, wb.y, wb.z, wb.w};
#pragma unroll
                    for (int e = 0; e < 4; ++e) {
                        const int j = jc * 4 + e;
                        float2 w1 = __half22float2(*(__half2*)&wax[e]);
                        unsigned long long wr1 = pk2(w1.x, w1.x);
                        unsigned long long wi1 = pk2(w1.y, w1.y);
                        P1 = ffma2(xrr[j], wr1, P1);
                        Q1 = ffma2(xii[j], wi1, Q1);
                        R1 = ffma2(xrr[j], wi1, R1);
                        S1 = ffma2(xii[j], wr1, S1);
                        float2 w2 = __half22float2(*(__half2*)&wbx[e]);
                        unsigned long long wr2 = pk2(w2.x, w2.x);
                        unsigned long long wi2 = pk2(w2.y, w2.y);
                        P2 = ffma2(xrr[j], wr2, P2);
                        Q2 = ffma2(xii[j], wi2, Q2);
                        R2 = ffma2(xrr[j], wi2, R2);
                        S2 = ffma2(xii[j], wr2, S2);
                    }
                }
                // Y[i] = (P - Q) + i (R + S);  lane .x = row A, lane .y = row B
                float2 p1 = upk2(P1), q1 = upk2(Q1), r1 = upk2(R1), s1 = upk2(S1);
                float2 p2 = upk2(P2), q2 = upk2(Q2), r2 = upk2(R2), s2 = upk2(S2);
                float arA = p1.x - q1.x, aiA = r1.x + s1.x;   // Y_A[ia]
                float brA = p2.x - q2.x, biA = r2.x + s2.x;   // Y_A[ib]
                float arB = p1.y - q1.y, aiB = r1.y + s1.y;   // Y_B[ia]
                float brB = p2.y - q2.y, biB = r2.y + s2.y;   // Y_B[ib]
                ZA[gg * GP + f] = __floats2half2_rn(arA - biA, aiA + brA);
                ZB[gg * GP + f] = __floats2half2_rn(arB - biB, aiB + brB);
                if (f > 0) {
                    ZA[gg * GP + 256 - f] = __floats2half2_rn(arA + biA, brA - aiA);
                    ZB[gg * GP + 256 - f] = __floats2half2_rn(arB + biB, brB - aiB);
                }
            }
            // Nyquist f=128: 2 rows x 16 real dot products on 32 threads (warp 0)
            if (t128 < 32) {
                __half2* Zr = (t128 < 16) ? ZA : ZB;
                const int i = t128 & 15;
                float xn[16];
#pragma unroll
                for (int p = 0; p < 8; ++p) {
                    float2 z = __half22float2(Zr[p * GP + 128]);
                    xn[2 * p] = z.x; xn[2 * p + 1] = z.y;
                }
                float acc = 0.f;
#pragma unroll
                for (int j = 0; j < 16; ++j)
                    acc += xn[j] * __low2float(Wcs[128 * 256 + i * 16 + j]);
                __syncwarp();
                ((__half*)(Zr + (i >> 1) * GP + 128))[i & 1] = __float2half(acc);
            }
        }
        BARS();

        // ---- inverse FFT-256 + bias + store, both rows ----
#pragma unroll
        for (int r = 0; r < 2; ++r) {
            __half2* gb = r ? gB : gA;
            inv256(gb, twf, t, re, im);
            float* orow = out + (size_t)(row + r) * DIN + (g << 9);
            const float* brow = bias + (g << 9);
#pragma unroll
            for (int k2 = 0; k2 < 16; ++k2) {
                int n = (k2 << 4) + t;
                orow[n]       = re[k2] + __ldg(brow + n);
                orow[n + 256] = im[k2] + __ldg(brow + n + 256);
            }
        }
        BARS();   // protect buffers before next iteration's P0
    }
#undef BARS
}

extern "C" void kernel_launch(void* const* d_in, const int* in_sizes, int n_in,
                              void* d_out, int out_size) {
    const float* x    = (const float*)d_in[0];
    const float* W    = (const float*)d_in[1];
    const float* d    = (const float*)d_in[2];
    const float* bias = (const float*)d_in[3];
    float* out = (float*)d_out;

    const size_t SMEM = 132096 + 2048 + 16384 + (size_t)8 * 8 * GP * sizeof(__half2); // 220160
    cudaFuncSetAttribute(bc_main, cudaFuncAttributeMaxDynamicSharedMemorySize, (int)SMEM);

    bc_wfft<<<K16 * K16, 256>>>(W);
    bc_main<<<152, TPB, SMEM>>>(x, d, bias, out);
    (void)in_sizes; (void)n_in; (void)out_size;
}